// round 1
// baseline (speedup 1.0000x reference)
#include <cuda_runtime.h>

// PlanarQuantMSE: per-row normalize, per-2D-group rotate, quantize to nearest
// of 16 sorted centroids, inverse-rotate, rescale. Outputs x_hat then indices
// (as float) concatenated, if out_size allows.

#define ROWS 4096
#define DIM  4096
#define TPB  256
#define VPT  4   // float4s per thread  (TPB*4*VPT == DIM)

__device__ __forceinline__ void quant16(float v, const float* __restrict__ c,
                                        int& idx, float& q) {
    float best = fabsf(v - c[0]);
    idx = 0;
    q = c[0];
#pragma unroll
    for (int i = 1; i < 16; i++) {
        float d = fabsf(v - c[i]);
        bool lt = d < best;           // strict < keeps lowest index on ties (argmin semantics)
        best = lt ? d : best;
        idx  = lt ? i : idx;
        q    = lt ? c[i] : q;
    }
}

__global__ __launch_bounds__(TPB)
void pq_kernel(const float* __restrict__ x,
               const float* __restrict__ cent,
               const float* __restrict__ rot2,
               float* __restrict__ xhat,
               float* __restrict__ idxout)   // may be null
{
    const int row = blockIdx.x;
    const int t   = threadIdx.x;

    const float4* xr = (const float4*)(x + (size_t)row * DIM);

    float4 v[VPT];
    float ss = 0.0f;
#pragma unroll
    for (int k = 0; k < VPT; k++) {
        v[k] = xr[t + k * TPB];
        ss += v[k].x * v[k].x + v[k].y * v[k].y
            + v[k].z * v[k].z + v[k].w * v[k].w;
    }

    // ---- block reduction of sum of squares ----
    __shared__ float red[TPB / 32];
    __shared__ float norm_sh;
#pragma unroll
    for (int o = 16; o > 0; o >>= 1)
        ss += __shfl_xor_sync(0xffffffffu, ss, o);
    if ((t & 31) == 0) red[t >> 5] = ss;
    __syncthreads();
    if (t < (TPB / 32)) {
        float s2 = red[t];
#pragma unroll
        for (int o = (TPB / 64); o > 0; o >>= 1)
            s2 += __shfl_xor_sync((1u << (TPB / 32)) - 1u, s2, o);
        if (t == 0) {
            float n = sqrtf(s2);
            norm_sh = fmaxf(n, 1e-8f);
        }
    }
    __syncthreads();
    const float norm = norm_sh;
    const float inv  = 1.0f / norm;

    // centroids -> registers (fully unrolled users keep them enregistered)
    float c[16];
#pragma unroll
    for (int i = 0; i < 16; i++) c[i] = __ldg(&cent[i]);

    const float4* rr = (const float4*)rot2;            // [1024] float4: (c,s,c,s)
    float4* xo = (float4*)(xhat + (size_t)row * DIM);
    float4* io = idxout ? (float4*)(idxout + (size_t)row * DIM) : nullptr;

#pragma unroll
    for (int k = 0; k < VPT; k++) {
        const int j = t + k * TPB;                     // float4 index in row
        const float4 rs = __ldg(&rr[j]);               // groups 2j (x,y) and 2j+1 (z,w)

        const float v0 = v[k].x * inv, v1 = v[k].y * inv;
        const float v2 = v[k].z * inv, v3 = v[k].w * inv;

        // forward rotation
        const float r0 = rs.x * v0 - rs.y * v1;
        const float r1 = rs.y * v0 + rs.x * v1;
        const float r2 = rs.z * v2 - rs.w * v3;
        const float r3 = rs.w * v2 + rs.z * v3;

        int   i0, i1, i2, i3;
        float q0, q1, q2, q3;
        quant16(r0, c, i0, q0);
        quant16(r1, c, i1, q1);
        quant16(r2, c, i2, q2);
        quant16(r3, c, i3, q3);

        // inverse rotation, rescale
        float4 out;
        out.x = (rs.x * q0 + rs.y * q1) * norm;
        out.y = (rs.x * q1 - rs.y * q0) * norm;
        out.z = (rs.z * q2 + rs.w * q3) * norm;
        out.w = (rs.z * q3 - rs.w * q2) * norm;
        xo[j] = out;

        if (io) {
            float4 fo;
            fo.x = (float)i0; fo.y = (float)i1;
            fo.z = (float)i2; fo.w = (float)i3;
            io[j] = fo;
        }
    }
}

extern "C" void kernel_launch(void* const* d_in, const int* in_sizes, int n_in,
                              void* d_out, int out_size) {
    // Identify inputs by element count (robust to metadata order):
    //   x: 16777216, centroids: 16, rot2: 4096
    const float* x = nullptr;
    const float* cent = nullptr;
    const float* rot2 = nullptr;
    for (int i = 0; i < n_in; i++) {
        if (in_sizes[i] == ROWS * DIM)      x    = (const float*)d_in[i];
        else if (in_sizes[i] == 16)         cent = (const float*)d_in[i];
        else if (in_sizes[i] == 2048 * 2)   rot2 = (const float*)d_in[i];
    }

    float* xhat = (float*)d_out;
    float* idxf = nullptr;
    const long long n = (long long)ROWS * DIM;
    if ((long long)out_size >= 2 * n) idxf = xhat + n;   // concatenated (x_hat, indices)

    pq_kernel<<<ROWS, TPB>>>(x, cent, rot2, xhat, idxf);
}

// round 2
// speedup vs baseline: 2.8074x; 2.8074x over previous
#include <cuda_runtime.h>

// PlanarQuantMSE: per-row normalize, per-2D-group rotate, quantize to nearest
// of 16 SORTED centroids, inverse-rotate, rescale.
// Output: [x_hat | indices-as-float] concatenated (confirmed in R1).
//
// Quantization strategy: idx(v) = #{ midpoints m_j < v }. A 4096-cell LUT over
// v in [-1,1] (v is a component of a rotated unit-subvector, so |v| <= 1) gives
// L = #{ m_j in cells < cell(v) }; one compare against mid[L] finishes the job,
// exact as long as no cell holds >= 2 midpoints (setup kernel verifies; sets a
// flag to force the 15-compare fallback otherwise).

#define ROWS 4096
#define DIM  4096
#define TPB  256
#define VPT  4        // float4s per thread (TPB*4*VPT == DIM)
#define NCELL 4096
#define SCALEF 1820.0f
// magic = 2^23*1.5 + 2275 ; t = bits(fma(v,S,magic)) - 0x4B400000 = round(v*S)+2275
#define MAGICF 12585187.0f
#define BITBASE 0x4B400000

__device__ unsigned char g_lut[NCELL];
__device__ float g_mid[16];     // m[0..14], m[15] = big sentinel
__device__ int   g_flag;

__global__ void setup_kernel(const float* __restrict__ cent) {
    __shared__ float m[15];
    __shared__ int   tc[15];
    const int t = threadIdx.x;
    if (t < 15) {
        float mm = 0.5f * (cent[t] + cent[t + 1]);
        m[t] = mm;
        g_mid[t] = mm;
        tc[t] = __float_as_int(fmaf(mm, SCALEF, MAGICF)) - BITBASE;
    }
    if (t == 15) g_mid[15] = 3.0e38f;
    __syncthreads();
    if (t == 0) {
        int fl = 0;
        for (int j = 1; j < 15; j++)
            if (tc[j] == tc[j - 1]) fl = 1;
        g_flag = fl;
    }
    for (int k = t; k < NCELL; k += blockDim.x) {
        int L = 0;
#pragma unroll
        for (int j = 0; j < 15; j++) L += (tc[j] < k) ? 1 : 0;
        g_lut[k] = (unsigned char)L;
    }
}

__device__ __forceinline__ void quant(float v,
                                      const unsigned char* __restrict__ lut,
                                      const float* __restrict__ mid,
                                      const float* __restrict__ csh,
                                      const float* __restrict__ fidx,
                                      int flag, float& q, float& fi) {
    int idx;
    if (!flag) {
        int t = __float_as_int(fmaf(v, SCALEF, MAGICF)) - BITBASE;
        t = min(max(t, 0), NCELL - 1);
        idx = (int)lut[t];
        idx += (v > mid[idx]) ? 1 : 0;
    } else {
        idx = 0;
#pragma unroll
        for (int j = 0; j < 15; j++) idx += (v > mid[j]) ? 1 : 0;
    }
    q  = csh[idx];
    fi = fidx[idx];
}

__global__ __launch_bounds__(TPB)
void pq_kernel(const float* __restrict__ x,
               const float* __restrict__ cent,
               const float* __restrict__ rot2,
               float* __restrict__ xhat,
               float* __restrict__ idxout)
{
    __shared__ unsigned char lut_sh[NCELL];
    __shared__ float mid_sh[16];
    __shared__ float c_sh[16];
    __shared__ float fidx_sh[16];
    __shared__ float red[TPB / 32];
    __shared__ float norm_sh;
    __shared__ int   flag_sh;

    const int row = blockIdx.x;
    const int t   = threadIdx.x;

    // stage tables into shared (covered by the reduction's __syncthreads)
    ((int4*)lut_sh)[t] = ((const int4*)g_lut)[t];          // 256 * 16B = 4096B
    if (t < 16) {
        mid_sh[t]  = g_mid[t];
        c_sh[t]    = __ldg(&cent[t]);
        fidx_sh[t] = (float)t;
    }
    if (t == 0) flag_sh = g_flag;

    const float4* xr = (const float4*)(x + (size_t)row * DIM);

    float4 v[VPT];
    float ss = 0.0f;
#pragma unroll
    for (int k = 0; k < VPT; k++) {
        v[k] = xr[t + k * TPB];
        ss += v[k].x * v[k].x + v[k].y * v[k].y
            + v[k].z * v[k].z + v[k].w * v[k].w;
    }

#pragma unroll
    for (int o = 16; o > 0; o >>= 1)
        ss += __shfl_xor_sync(0xffffffffu, ss, o);
    if ((t & 31) == 0) red[t >> 5] = ss;
    __syncthreads();
    if (t < (TPB / 32)) {
        float s2 = red[t];
#pragma unroll
        for (int o = (TPB / 64); o > 0; o >>= 1)
            s2 += __shfl_xor_sync((1u << (TPB / 32)) - 1u, s2, o);
        if (t == 0) norm_sh = fmaxf(sqrtf(s2), 1e-8f);
    }
    __syncthreads();
    const float norm = norm_sh;
    const float inv  = 1.0f / norm;
    const int   flag = flag_sh;

    const float4* rr = (const float4*)rot2;     // (c,s,c,s) per float4
    float4* xo = (float4*)(xhat + (size_t)row * DIM);
    float4* io = (float4*)(idxout + (size_t)row * DIM);

#pragma unroll
    for (int k = 0; k < VPT; k++) {
        const int j = t + k * TPB;
        const float4 rs = __ldg(&rr[j]);

        const float v0 = v[k].x * inv, v1 = v[k].y * inv;
        const float v2 = v[k].z * inv, v3 = v[k].w * inv;

        const float r0 = rs.x * v0 - rs.y * v1;
        const float r1 = rs.y * v0 + rs.x * v1;
        const float r2 = rs.z * v2 - rs.w * v3;
        const float r3 = rs.w * v2 + rs.z * v3;

        float q0, q1, q2, q3, f0, f1, f2, f3;
        quant(r0, lut_sh, mid_sh, c_sh, fidx_sh, flag, q0, f0);
        quant(r1, lut_sh, mid_sh, c_sh, fidx_sh, flag, q1, f1);
        quant(r2, lut_sh, mid_sh, c_sh, fidx_sh, flag, q2, f2);
        quant(r3, lut_sh, mid_sh, c_sh, fidx_sh, flag, q3, f3);

        float4 out;
        out.x = (rs.x * q0 + rs.y * q1) * norm;
        out.y = (rs.x * q1 - rs.y * q0) * norm;
        out.z = (rs.z * q2 + rs.w * q3) * norm;
        out.w = (rs.z * q3 - rs.w * q2) * norm;
        xo[j] = out;

        float4 fo;
        fo.x = f0; fo.y = f1; fo.z = f2; fo.w = f3;
        io[j] = fo;
    }
}

extern "C" void kernel_launch(void* const* d_in, const int* in_sizes, int n_in,
                              void* d_out, int out_size) {
    const float* x = nullptr;
    const float* cent = nullptr;
    const float* rot2 = nullptr;
    for (int i = 0; i < n_in; i++) {
        if (in_sizes[i] == ROWS * DIM)    x    = (const float*)d_in[i];
        else if (in_sizes[i] == 16)       cent = (const float*)d_in[i];
        else if (in_sizes[i] == 4096)     rot2 = (const float*)d_in[i];
    }

    float* xhat = (float*)d_out;
    float* idxf = xhat + (long long)ROWS * DIM;

    setup_kernel<<<1, 64>>>(cent);
    pq_kernel<<<ROWS, TPB>>>(x, cent, rot2, xhat, idxf);
}

// round 3
// speedup vs baseline: 3.1053x; 1.1061x over previous
#include <cuda_runtime.h>

// PlanarQuantMSE, single fused kernel.
// Per-row normalize, per-2D-group rotate, quantize to nearest of 16 SORTED
// centroids (1024-cell LUT + 1 correction compare; exact unless a cell holds
// >=2 midpoints, which a per-block flag detects -> 15-compare fallback),
// inverse-rotate, rescale. Output: [x_hat | indices-as-float] concatenated.

#define ROWS 4096
#define DIM  4096
#define TPB  256
#define VPT  4        // float4s per thread (TPB*4*VPT == DIM)
#define NCELL 1024
#define SCALEF 455.0f
// magic = 2^23*1.5 + 512 ; cell = bits(fma(v,S,magic)) - 0x4B400000 = round(v*S)+512
#define MAGICF 12583424.0f
#define BITBASE 0x4B400000

__device__ __forceinline__ void quant(float v,
                                      const unsigned char* __restrict__ lut,
                                      const float* __restrict__ mid,
                                      const float* __restrict__ csh,
                                      int flag, float& q, float& fi) {
    int idx;
    if (!flag) {
        int cell = __float_as_int(fmaf(v, SCALEF, MAGICF)) - BITBASE;
        cell = min(max(cell, 0), NCELL - 1);
        idx = (int)lut[cell];
        idx += (v > mid[idx]) ? 1 : 0;     // strict >: argmin lowest-index ties
    } else {
        idx = 0;
#pragma unroll
        for (int j = 0; j < 15; j++) idx += (v > mid[j]) ? 1 : 0;
    }
    q  = csh[idx];
    fi = (float)idx;
}

__global__ __launch_bounds__(TPB)
void pq_kernel(const float* __restrict__ x,
               const float* __restrict__ cent,
               const float* __restrict__ rot2,
               float* __restrict__ xhat,
               float* __restrict__ idxout)
{
    __shared__ unsigned char lut_sh[NCELL];
    __shared__ float mid_sh[16];
    __shared__ float c_sh[16];
    __shared__ int   tc_sh[15];
    __shared__ float red[TPB / 32];
    __shared__ float norm_sh;
    __shared__ int   flag_sh;

    const int row = blockIdx.x;
    const int t   = threadIdx.x;

    // ---- issue x loads first so DRAM streams while we do table setup ----
    const float4* xr = (const float4*)(x + (size_t)row * DIM);
    float4 v[VPT];
#pragma unroll
    for (int k = 0; k < VPT; k++) v[k] = xr[t + k * TPB];

    // ---- warp-0 table setup: centroids, midpoints, cell ids, dup flag ----
    if (t < 16) {
        float cv = __ldg(&cent[t]);
        c_sh[t] = cv;
        float cn = __shfl_down_sync(0x0000ffffu, cv, 1);
        float mm = 0.5f * (cv + cn);
        int cell = __float_as_int(fmaf(mm, SCALEF, MAGICF)) - BITBASE;
        if (t < 15) { mid_sh[t] = mm; tc_sh[t] = cell; }
        else        { mid_sh[15] = 3.0e38f; }
        int celln = __shfl_down_sync(0x0000ffffu, cell, 1);
        unsigned dup = __ballot_sync(0x0000ffffu, (t < 14) && (cell == celln));
        if (t == 0) flag_sh = (dup != 0u) ? 1 : 0;
    }

    // ---- row sum of squares ----
    float ss = 0.0f;
#pragma unroll
    for (int k = 0; k < VPT; k++)
        ss += v[k].x * v[k].x + v[k].y * v[k].y
            + v[k].z * v[k].z + v[k].w * v[k].w;
#pragma unroll
    for (int o = 16; o > 0; o >>= 1)
        ss += __shfl_xor_sync(0xffffffffu, ss, o);
    if ((t & 31) == 0) red[t >> 5] = ss;
    __syncthreads();                                   // barrier A

    // ---- LUT build (4 cells/thread, one packed STS.32; overlaps final reduce) ----
    {
        int tcr[15];
#pragma unroll
        for (int j = 0; j < 15; j++) tcr[j] = tc_sh[j];
        const int base = t * 4;
        int L0 = 0, L1 = 0, L2 = 0, L3 = 0;
#pragma unroll
        for (int j = 0; j < 15; j++) {
            int cj = tcr[j];
            L0 += (cj < base)     ? 1 : 0;
            L1 += (cj < base + 1) ? 1 : 0;
            L2 += (cj < base + 2) ? 1 : 0;
            L3 += (cj < base + 3) ? 1 : 0;
        }
        ((unsigned int*)lut_sh)[t] =
            (unsigned)L0 | ((unsigned)L1 << 8) | ((unsigned)L2 << 16) | ((unsigned)L3 << 24);
    }

    if (t < (TPB / 32)) {
        float s2 = red[t];
#pragma unroll
        for (int o = (TPB / 64); o > 0; o >>= 1)
            s2 += __shfl_xor_sync((1u << (TPB / 32)) - 1u, s2, o);
        if (t == 0) norm_sh = fmaxf(sqrtf(s2), 1e-8f);
    }
    __syncthreads();                                   // barrier B

    const float norm = norm_sh;
    const float inv  = 1.0f / norm;
    const int   flag = flag_sh;

    const float4* rr = (const float4*)rot2;            // (c,s,c,s) per float4
    float4* xo = (float4*)(xhat  + (size_t)row * DIM);
    float4* io = (float4*)(idxout + (size_t)row * DIM);

#pragma unroll
    for (int k = 0; k < VPT; k++) {
        const int j = t + k * TPB;
        const float4 rs = __ldg(&rr[j]);

        const float v0 = v[k].x * inv, v1 = v[k].y * inv;
        const float v2 = v[k].z * inv, v3 = v[k].w * inv;

        const float r0 = rs.x * v0 - rs.y * v1;
        const float r1 = rs.y * v0 + rs.x * v1;
        const float r2 = rs.z * v2 - rs.w * v3;
        const float r3 = rs.w * v2 + rs.z * v3;

        float q0, q1, q2, q3, f0, f1, f2, f3;
        quant(r0, lut_sh, mid_sh, c_sh, flag, q0, f0);
        quant(r1, lut_sh, mid_sh, c_sh, flag, q1, f1);
        quant(r2, lut_sh, mid_sh, c_sh, flag, q2, f2);
        quant(r3, lut_sh, mid_sh, c_sh, flag, q3, f3);

        float4 out;
        out.x = (rs.x * q0 + rs.y * q1) * norm;
        out.y = (rs.x * q1 - rs.y * q0) * norm;
        out.z = (rs.z * q2 + rs.w * q3) * norm;
        out.w = (rs.z * q3 - rs.w * q2) * norm;
        __stcs(&xo[j], out);

        float4 fo;
        fo.x = f0; fo.y = f1; fo.z = f2; fo.w = f3;
        __stcs(&io[j], fo);
    }
}

extern "C" void kernel_launch(void* const* d_in, const int* in_sizes, int n_in,
                              void* d_out, int out_size) {
    const float* x = nullptr;
    const float* cent = nullptr;
    const float* rot2 = nullptr;
    for (int i = 0; i < n_in; i++) {
        if (in_sizes[i] == ROWS * DIM) x    = (const float*)d_in[i];
        else if (in_sizes[i] == 16)    cent = (const float*)d_in[i];
        else if (in_sizes[i] == 4096)  rot2 = (const float*)d_in[i];
    }

    float* xhat = (float*)d_out;
    float* idxf = xhat + (long long)ROWS * DIM;

    pq_kernel<<<ROWS, TPB>>>(x, cent, rot2, xhat, idxf);
}